// round 8
// baseline (speedup 1.0000x reference)
#include <cuda_runtime.h>
#include <cuda_fp16.h>
#include <cstdint>

// Problem constants: B=32, N=1024, C=128, L=4
#define BB 32
#define NN 1024
#define CC 128
#define LL 4
#define ROWS (BB * NN)          // 32768
#define HSZ  (ROWS * CC)
#define GSZ  (ROWS * 3 * CC)

// fp32 scratch
__device__ __align__(16) float g_gx[GSZ];
__device__ __align__(16) float g_gh[GSZ];
// fp16 scratch
__device__ __align__(16) __half g_adjT[(size_t)BB * NN * NN];   // [b][n][j] exact
__device__ __align__(16) __half g_hT_hi[HSZ];                   // [c][b*N+j]
__device__ __align__(16) __half g_hT_lo[HSZ];
__device__ __align__(16) __half g_hA_hi[HSZ];                   // h splits (ping)
__device__ __align__(16) __half g_hA_lo[HSZ];
__device__ __align__(16) __half g_hB_hi[HSZ];                   // h splits (pong)
__device__ __align__(16) __half g_hB_lo[HSZ];
__device__ __align__(16) __half g_s_hi[HSZ];                    // s = adjT@h splits
__device__ __align__(16) __half g_s_lo[HSZ];
__device__ __align__(16) __half g_Vt_hi[LL * 3 * CC * CC];      // [l][g][c]  V^T
__device__ __align__(16) __half g_Vt_lo[LL * 3 * CC * CC];
__device__ __align__(16) __half g_whh_hi[LL * 3 * CC * CC];
__device__ __align__(16) __half g_whh_lo[LL * 3 * CC * CC];

// ===========================================================================
// helpers
// ===========================================================================
__device__ __forceinline__ uint32_t smem_u32(const void* p) {
    uint32_t a;
    asm("{ .reg .u64 t; cvta.to.shared.u64 t, %1; cvt.u32.u64 %0, t; }"
        : "=r"(a) : "l"(p));
    return a;
}
__device__ __forceinline__ void cp16(uint32_t s, const void* g) {
    asm volatile("cp.async.cg.shared.global [%0], [%1], 16;" :: "r"(s), "l"(g));
}
#define CP_COMMIT() asm volatile("cp.async.commit_group;" ::: "memory")
#define CP_WAIT(n)  asm volatile("cp.async.wait_group %0;" :: "n"(n) : "memory")

#define LDSM4(R0, R1, R2, R3, ADDR)                                          \
    asm volatile("ldmatrix.sync.aligned.m8n8.x4.shared.b16 {%0,%1,%2,%3}, [%4];" \
                 : "=r"(R0), "=r"(R1), "=r"(R2), "=r"(R3) : "r"(ADDR))

#define MMA16816(D, A, B0, B1)                                               \
    asm volatile(                                                            \
        "mma.sync.aligned.m16n8k16.row.col.f32.f16.f16.f32 "                 \
        "{%0,%1,%2,%3},{%4,%5,%6,%7},{%8,%9},{%0,%1,%2,%3};"                 \
        : "+f"((D)[0]), "+f"((D)[1]), "+f"((D)[2]), "+f"((D)[3])             \
        : "r"((A)[0]), "r"((A)[1]), "r"((A)[2]), "r"((A)[3]),                \
          "r"(B0), "r"(B1))

// Load an R-row x 64-col fp16 tile (128B rows, XOR-16B swizzle) via cp.async.
template <int R>
__device__ __forceinline__ void cp_tile(const __half* __restrict__ g,
                                        int stride, uint32_t sdst, int t, int kc)
{
    #pragma unroll
    for (int u = 0; u < R / 32; ++u) {
        const int unit = t + u * 256;
        const int row  = unit >> 3;
        const int c16  = unit & 7;
        const uint32_t sw = ((row << 7) + (c16 << 4)) ^ ((row & 7) << 4);
        cp16(sdst + sw, g + (size_t)row * stride + (kc << 6) + (c16 << 3));
    }
}

// ===========================================================================
// adj GEMM: CTA 256x128, warp 64x64, 3-stage pipeline.
//   C = A @ (Bhi + Blo)^T  (A exact fp16), out: fp16 hi/lo split
// ===========================================================================
__global__ __launch_bounds__(256)
void adj_mma(const __half* __restrict__ a, const __half* __restrict__ b_hi,
             const __half* __restrict__ b_lo,
             __half* __restrict__ Chi, __half* __restrict__ Clo,
             int K, int lda, int ldb, int ldc,
             long sA, long sB, long sC)
{
    constexpr uint32_t ATSZ = 32768;
    constexpr uint32_t BTSZ = 16384;
    constexpr uint32_t STG  = ATSZ + 2 * BTSZ;   // 64 KB, 3 stages = 192 KB
    extern __shared__ __align__(128) char smem[];
    const uint32_t sbase = smem_u32(smem);

    const int t     = threadIdx.x;
    const int lane  = t & 31;
    const int warp  = t >> 5;
    const int mwarp = (warp >> 1) * 64;
    const int nwarp = (warp & 1) * 64;
    const int m0 = blockIdx.y * 256;
    const int n0 = blockIdx.x * 128;
    const int z  = blockIdx.z;

    const __half* Ag = a    + (size_t)z * sA + (size_t)m0 * lda;
    const __half* Bh = b_hi + (size_t)z * sB + (size_t)n0 * ldb;
    const __half* Bl = b_lo + (size_t)z * sB + (size_t)n0 * ldb;

    const int NC = K >> 6;

    float acc[4][8][4];
    #pragma unroll
    for (int i = 0; i < 4; i++)
        #pragma unroll
        for (int j = 0; j < 8; j++)
            #pragma unroll
            for (int q = 0; q < 4; q++)
                acc[i][j][q] = 0.0f;

    auto load_stage = [&](int kc, uint32_t sb) {
        cp_tile<256>(Ag, lda, sb, t, kc);
        cp_tile<128>(Bh, ldb, sb + ATSZ, t, kc);
        cp_tile<128>(Bl, ldb, sb + ATSZ + BTSZ, t, kc);
        CP_COMMIT();
    };

    load_stage(0, sbase);
    load_stage(1, sbase + STG);

    for (int c = 0; c < NC; ++c) {
        const int nxt = c + 2;
        if (nxt < NC) load_stage(nxt, sbase + (nxt % 3) * STG);
        const int nleft = NC - 1 - c;
        if (nleft >= 2)      CP_WAIT(2);
        else if (nleft == 1) CP_WAIT(1);
        else                 CP_WAIT(0);
        __syncthreads();

        const uint32_t S = sbase + (c % 3) * STG;
        const uint32_t Bb = S + ATSZ;

        #pragma unroll
        for (int ks = 0; ks < 4; ++ks) {
            uint32_t ah[4][4];
            #pragma unroll
            for (int mb = 0; mb < 4; ++mb) {
                const int row = mwarp + mb * 16 + (lane & 15);
                const int col = ks * 32 + ((lane >> 4) << 4);
                const uint32_t sw = (row << 7) + (col ^ ((row & 7) << 4));
                LDSM4(ah[mb][0], ah[mb][1], ah[mb][2], ah[mb][3], S + sw);
            }
            uint32_t bh[4][4], bl[4][4];
            #pragma unroll
            for (int nq = 0; nq < 4; ++nq) {
                const int row = nwarp + nq * 16 + ((lane >> 4) << 3) + (lane & 7);
                const int col = ks * 32 + (((lane >> 3) & 1) << 4);
                const uint32_t sw = (row << 7) + (col ^ ((row & 7) << 4));
                LDSM4(bh[nq][0], bh[nq][1], bh[nq][2], bh[nq][3], Bb + sw);
                LDSM4(bl[nq][0], bl[nq][1], bl[nq][2], bl[nq][3], Bb + BTSZ + sw);
            }
            #pragma unroll
            for (int mb = 0; mb < 4; ++mb)
                #pragma unroll
                for (int n = 0; n < 8; ++n) {
                    const int q0 = (n & 1) * 2;
                    MMA16816(acc[mb][n], ah[mb], bh[n >> 1][q0], bh[n >> 1][q0 + 1]);
                    MMA16816(acc[mb][n], ah[mb], bl[n >> 1][q0], bl[n >> 1][q0 + 1]);
                }
        }
        __syncthreads();
    }

    // epilogue: fp16 hi/lo
    const int rbase = m0 + mwarp + (lane >> 2);
    const int cbase = n0 + nwarp + (lane & 3) * 2;
    __half* CH = Chi + (size_t)z * sC;
    __half* CL = Clo + (size_t)z * sC;
    #pragma unroll
    for (int mb = 0; mb < 4; ++mb) {
        #pragma unroll
        for (int n = 0; n < 8; ++n) {
            const int gc = cbase + n * 8;
            const int r  = rbase + mb * 16;
            #pragma unroll
            for (int hf = 0; hf < 2; ++hf) {
                const float v0 = acc[mb][n][hf * 2 + 0];
                const float v1 = acc[mb][n][hf * 2 + 1];
                const __half h0 = __float2half_rn(v0);
                const __half h1 = __float2half_rn(v1);
                __half2 ph; ph.x = h0; ph.y = h1;
                __half2 pl;
                pl.x = __float2half_rn(v0 - __half2float(h0));
                pl.y = __float2half_rn(v1 - __half2float(h1));
                const size_t off = (size_t)(r + hf * 8) * ldc + gc;
                *reinterpret_cast<__half2*>(&CH[off]) = ph;
                *reinterpret_cast<__half2*>(&CL[off]) = pl;
            }
        }
    }
}

// ===========================================================================
// Merged gate GEMMs: grid.z selects (A,B,C,bias) set.
//   C = Ahi@Bhi^T + Ahi@Blo^T + Alo@Bhi^T + bias   (fp32 out, ldc=384)
// CTA 256x128, warp 64x64, 2-stage. K=128 (NC=2).
// ===========================================================================
__global__ __launch_bounds__(256)
void gate_mma(const __half* __restrict__ a0h, const __half* __restrict__ a0l,
              const __half* __restrict__ b0h, const __half* __restrict__ b0l,
              float* __restrict__ C0, const float* __restrict__ bias0,
              const __half* __restrict__ a1h, const __half* __restrict__ a1l,
              const __half* __restrict__ b1h, const __half* __restrict__ b1l,
              float* __restrict__ C1, const float* __restrict__ bias1)
{
    constexpr uint32_t ATSZ = 32768;
    constexpr uint32_t BTSZ = 16384;
    constexpr uint32_t STG  = 2 * ATSZ + 2 * BTSZ;   // 96 KB, 2 stages = 192 KB
    extern __shared__ __align__(128) char smem[];
    const uint32_t sbase = smem_u32(smem);

    const int t     = threadIdx.x;
    const int lane  = t & 31;
    const int warp  = t >> 5;
    const int mwarp = (warp >> 1) * 64;
    const int nwarp = (warp & 1) * 64;
    const int m0 = blockIdx.y * 256;
    const int n0 = blockIdx.x * 128;
    const int z  = blockIdx.z;

    const __half* Ah = (z == 0 ? a0h : a1h) + (size_t)m0 * CC;
    const __half* Al = (z == 0 ? a0l : a1l) + (size_t)m0 * CC;
    const __half* Bh = (z == 0 ? b0h : b1h) + (size_t)n0 * CC;
    const __half* Bl = (z == 0 ? b0l : b1l) + (size_t)n0 * CC;
    float* C = (z == 0 ? C0 : C1);
    const float* bias = (z == 0 ? bias0 : bias1);

    constexpr int NC = 2;   // K = 128

    float acc[4][8][4];
    #pragma unroll
    for (int i = 0; i < 4; i++)
        #pragma unroll
        for (int j = 0; j < 8; j++)
            #pragma unroll
            for (int q = 0; q < 4; q++)
                acc[i][j][q] = 0.0f;

    auto load_stage = [&](int kc, uint32_t sb) {
        cp_tile<256>(Ah, CC, sb, t, kc);
        cp_tile<256>(Al, CC, sb + ATSZ, t, kc);
        cp_tile<128>(Bh, CC, sb + 2 * ATSZ, t, kc);
        cp_tile<128>(Bl, CC, sb + 2 * ATSZ + BTSZ, t, kc);
        CP_COMMIT();
    };

    load_stage(0, sbase);
    load_stage(1, sbase + STG);

    #pragma unroll
    for (int c = 0; c < NC; ++c) {
        if (c == 0) CP_WAIT(1); else CP_WAIT(0);
        __syncthreads();

        const uint32_t S = sbase + c * STG;
        const uint32_t Bb = S + 2 * ATSZ;

        #pragma unroll
        for (int ks = 0; ks < 4; ++ks) {
            uint32_t ah[4][4], al[4][4];
            #pragma unroll
            for (int mb = 0; mb < 4; ++mb) {
                const int row = mwarp + mb * 16 + (lane & 15);
                const int col = ks * 32 + ((lane >> 4) << 4);
                const uint32_t sw = (row << 7) + (col ^ ((row & 7) << 4));
                LDSM4(ah[mb][0], ah[mb][1], ah[mb][2], ah[mb][3], S + sw);
                LDSM4(al[mb][0], al[mb][1], al[mb][2], al[mb][3], S + ATSZ + sw);
            }
            uint32_t bh[4][4], bl[4][4];
            #pragma unroll
            for (int nq = 0; nq < 4; ++nq) {
                const int row = nwarp + nq * 16 + ((lane >> 4) << 3) + (lane & 7);
                const int col = ks * 32 + (((lane >> 3) & 1) << 4);
                const uint32_t sw = (row << 7) + (col ^ ((row & 7) << 4));
                LDSM4(bh[nq][0], bh[nq][1], bh[nq][2], bh[nq][3], Bb + sw);
                LDSM4(bl[nq][0], bl[nq][1], bl[nq][2], bl[nq][3], Bb + BTSZ + sw);
            }
            #pragma unroll
            for (int mb = 0; mb < 4; ++mb)
                #pragma unroll
                for (int n = 0; n < 8; ++n) {
                    const int q0 = (n & 1) * 2;
                    MMA16816(acc[mb][n], ah[mb], bh[n >> 1][q0], bh[n >> 1][q0 + 1]);
                    MMA16816(acc[mb][n], ah[mb], bl[n >> 1][q0], bl[n >> 1][q0 + 1]);
                    MMA16816(acc[mb][n], al[mb], bh[n >> 1][q0], bh[n >> 1][q0 + 1]);
                }
        }
        __syncthreads();
    }

    const int rbase = m0 + mwarp + (lane >> 2);
    const int cbase = n0 + nwarp + (lane & 3) * 2;
    #pragma unroll
    for (int mb = 0; mb < 4; ++mb) {
        #pragma unroll
        for (int n = 0; n < 8; ++n) {
            const int gc = cbase + n * 8;
            const float bx = bias[gc];
            const float by = bias[gc + 1];
            const int r = rbase + mb * 16;
            float2 v0 = { acc[mb][n][0] + bx, acc[mb][n][1] + by };
            float2 v1 = { acc[mb][n][2] + bx, acc[mb][n][3] + by };
            *reinterpret_cast<float2*>(&C[(size_t)r * (3 * CC) + gc])       = v0;
            *reinterpret_cast<float2*>(&C[(size_t)(r + 8) * (3 * CC) + gc]) = v1;
        }
    }
}

// ===========================================================================
// Prep kernels
// ===========================================================================
__global__ __launch_bounds__(256)
void adj_transpose(const float* __restrict__ adj, __half* __restrict__ adjT)
{
    __shared__ float tile[32][33];
    const int b  = blockIdx.z;
    const int j0 = blockIdx.x * 32;
    const int n0 = blockIdx.y * 32;
    const float* src = adj + (size_t)b * NN * NN;
    __half* dst = adjT + (size_t)b * NN * NN;
    const int tx = threadIdx.x & 31, ty = threadIdx.x >> 5;
    #pragma unroll
    for (int r = ty; r < 32; r += 8)
        tile[r][tx] = src[(size_t)(j0 + r) * NN + n0 + tx];
    __syncthreads();
    #pragma unroll
    for (int r = ty; r < 32; r += 8)
        dst[(size_t)(n0 + r) * NN + j0 + tx] = __float2half_rn(tile[tx][r]);
}

__global__ __launch_bounds__(256)
void split2(const float* __restrict__ x,
            __half* __restrict__ hi, __half* __restrict__ lo)
{
    const int i = blockIdx.x * blockDim.x + threadIdx.x;
    const float v = x[i];
    const __half h = __float2half_rn(v);
    hi[i] = h;
    lo[i] = __float2half_rn(v - __half2float(h));
}

// Vt[l][g][c] = sum_d w_ih[l][g][d] * W[l][c][d], split hi/lo.
__global__ __launch_bounds__(256)
void vt_prep(const float* __restrict__ W, const float* __restrict__ w_ih,
             __half* __restrict__ Vthi, __half* __restrict__ Vtlo)
{
    const int l   = blockIdx.z;
    const int idx = blockIdx.x * 256 + threadIdx.x;   // < 384*128
    const int g = idx >> 7;
    const int c = idx & 127;
    const float* wi = w_ih + (size_t)l * 3 * CC * CC + (size_t)g * CC;
    const float* wc = W    + (size_t)l * CC * CC + (size_t)c * CC;
    float s = 0.0f;
    #pragma unroll 8
    for (int d = 0; d < CC; ++d)
        s = fmaf(wi[d], wc[d], s);
    const __half h = __float2half_rn(s);
    const size_t o = (size_t)l * 3 * CC * CC + idx;
    Vthi[o] = h;
    Vtlo[o] = __float2half_rn(s - __half2float(h));
}

// x_prep: x fp32 [row][c] -> h hi/lo row-major + hT hi/lo [c][row]
__global__ __launch_bounds__(256)
void x_prep(const float* __restrict__ x,
            __half* __restrict__ hhi, __half* __restrict__ hlo,
            __half* __restrict__ hThi, __half* __restrict__ hTlo)
{
    __shared__ float sv[64][129];
    const int r0 = blockIdx.x * 64;
    const int t  = threadIdx.x;
    #pragma unroll
    for (int k = 0; k < 32; ++k) {
        const int li  = t + k * 256;           // 0..8191
        const int rl  = li >> 7;
        const int c   = li & 127;
        const int idx = (r0 + rl) * CC + c;
        const float v = x[idx];
        const __half h = __float2half_rn(v);
        hhi[idx] = h;
        hlo[idx] = __float2half_rn(v - __half2float(h));
        sv[rl][c] = v;
    }
    __syncthreads();
    const int cr = t >> 1;
    const int hb = (t & 1) * 32;
    #pragma unroll
    for (int v2 = 0; v2 < 16; ++v2) {
        const float f0 = sv[hb + v2 * 2 + 0][cr];
        const float f1 = sv[hb + v2 * 2 + 1][cr];
        const __half h0 = __float2half_rn(f0);
        const __half h1 = __float2half_rn(f1);
        __half2 ph; ph.x = h0; ph.y = h1;
        __half2 pl;
        pl.x = __float2half_rn(f0 - __half2float(h0));
        pl.y = __float2half_rn(f1 - __half2float(h1));
        const size_t o = (size_t)cr * ROWS + r0 + hb + v2 * 2;
        *reinterpret_cast<__half2*>(&hThi[o]) = ph;
        *reinterpret_cast<__half2*>(&hTlo[o]) = pl;
    }
}

// ===========================================================================
// Fused GRU: reads gx/gh fp32 + h splits; writes next h row-major hi/lo AND
// transposed hT hi/lo (via smem), or fp32 masked output on the last layer.
// One CTA = 64 rows.
// ===========================================================================
__global__ __launch_bounds__(256)
void gru_elem4(const float* __restrict__ gx, const float* __restrict__ gh,
               const __half* __restrict__ hhi_in, const __half* __restrict__ hlo_in,
               __half* __restrict__ hhi_out, __half* __restrict__ hlo_out,
               __half* __restrict__ hThi_out, __half* __restrict__ hTlo_out,
               float* __restrict__ outF,
               const float* __restrict__ mask, int isLast)
{
    __shared__ float sv[64][129];
    const int r0 = blockIdx.x * 64;
    const int t  = threadIdx.x;

    #pragma unroll
    for (int k = 0; k < 32; ++k) {
        const int li  = t + k * 256;
        const int rl  = li >> 7;
        const int c   = li & 127;
        const int row = r0 + rl;
        const int idx = row * CC + c;
        const long gb = (long)row * (3 * CC);

        const float xr = gx[gb + c];
        const float xz = gx[gb + CC + c];
        const float xn = gx[gb + 2 * CC + c];
        const float hr = gh[gb + c];
        const float hz = gh[gb + CC + c];
        const float hn = gh[gb + 2 * CC + c];

        const float h = __half2float(hhi_in[idx]) + __half2float(hlo_in[idx]);

        const float rg = 1.0f / (1.0f + __expf(-(xr + hr)));
        const float zg = 1.0f / (1.0f + __expf(-(xz + hz)));
        const float ng = tanhf(xn + rg * hn);
        const float hnew = (1.0f - zg) * ng + zg * h;

        if (isLast) {
            outF[idx] = hnew * mask[row];
        } else {
            const __half hb16 = __float2half_rn(hnew);
            hhi_out[idx] = hb16;
            hlo_out[idx] = __float2half_rn(hnew - __half2float(hb16));
            sv[rl][c] = hnew;
        }
    }

    if (!isLast) {
        __syncthreads();
        const int cr = t >> 1;
        const int hb = (t & 1) * 32;
        #pragma unroll
        for (int v2 = 0; v2 < 16; ++v2) {
            const float f0 = sv[hb + v2 * 2 + 0][cr];
            const float f1 = sv[hb + v2 * 2 + 1][cr];
            const __half h0 = __float2half_rn(f0);
            const __half h1 = __float2half_rn(f1);
            __half2 ph; ph.x = h0; ph.y = h1;
            __half2 pl;
            pl.x = __float2half_rn(f0 - __half2float(h0));
            pl.y = __float2half_rn(f1 - __half2float(h1));
            const size_t o = (size_t)cr * ROWS + r0 + hb + v2 * 2;
            *reinterpret_cast<__half2*>(&hThi_out[o]) = ph;
            *reinterpret_cast<__half2*>(&hTlo_out[o]) = pl;
        }
    }
}

// ===========================================================================
#define SMEM_ADJ   (3 * (32768 + 2 * 16384))         // 192 KB (3 stages)
#define SMEM_GATE  (2 * (2 * 32768 + 2 * 16384))     // 192 KB (2 stages)

extern "C" void kernel_launch(void* const* d_in, const int* in_sizes, int n_in,
                              void* d_out, int out_size)
{
    const float* x      = (const float*)d_in[0];
    const float* adj    = (const float*)d_in[1];
    const float* mask   = (const float*)d_in[2];
    const float* weight = (const float*)d_in[3];
    const float* w_ih   = (const float*)d_in[4];
    const float* w_hh   = (const float*)d_in[5];
    const float* b_ih   = (const float*)d_in[6];
    const float* b_hh   = (const float*)d_in[7];
    float* out = (float*)d_out;

    float *p_gx, *p_gh;
    __half *p_adjT, *p_hThi, *p_hTlo, *p_shi, *p_slo;
    __half *p_hAhi, *p_hAlo, *p_hBhi, *p_hBlo;
    __half *p_Vthi, *p_Vtlo, *p_whhhi, *p_whhlo;
    cudaGetSymbolAddress((void**)&p_gx, g_gx);
    cudaGetSymbolAddress((void**)&p_gh, g_gh);
    cudaGetSymbolAddress((void**)&p_adjT, g_adjT);
    cudaGetSymbolAddress((void**)&p_hThi, g_hT_hi);
    cudaGetSymbolAddress((void**)&p_hTlo, g_hT_lo);
    cudaGetSymbolAddress((void**)&p_shi, g_s_hi);
    cudaGetSymbolAddress((void**)&p_slo, g_s_lo);
    cudaGetSymbolAddress((void**)&p_hAhi, g_hA_hi);
    cudaGetSymbolAddress((void**)&p_hAlo, g_hA_lo);
    cudaGetSymbolAddress((void**)&p_hBhi, g_hB_hi);
    cudaGetSymbolAddress((void**)&p_hBlo, g_hB_lo);
    cudaGetSymbolAddress((void**)&p_Vthi, g_Vt_hi);
    cudaGetSymbolAddress((void**)&p_Vtlo, g_Vt_lo);
    cudaGetSymbolAddress((void**)&p_whhhi, g_whh_hi);
    cudaGetSymbolAddress((void**)&p_whhlo, g_whh_lo);

    cudaFuncSetAttribute(adj_mma,  cudaFuncAttributeMaxDynamicSharedMemorySize, SMEM_ADJ);
    cudaFuncSetAttribute(gate_mma, cudaFuncAttributeMaxDynamicSharedMemorySize, SMEM_GATE);

    // ---- once per call ----
    adj_transpose<<<dim3(NN / 32, NN / 32, BB), 256>>>(adj, p_adjT);
    vt_prep<<<dim3((3 * CC * CC) / 256, 1, LL), 256>>>(weight, w_ih, p_Vthi, p_Vtlo);
    split2<<<(LL * 3 * CC * CC) / 256, 256>>>(w_hh, p_whhhi, p_whhlo);
    x_prep<<<ROWS / 64, 256>>>(x, p_hAhi, p_hAlo, p_hThi, p_hTlo);

    __half* hs_hi[2] = { p_hAhi, p_hBhi };
    __half* hs_lo[2] = { p_hAlo, p_hBlo };

    for (int l = 0; l < LL; l++) {
        __half* chi = hs_hi[l & 1];
        __half* clo = hs_lo[l & 1];
        __half* nhi = hs_hi[(l + 1) & 1];
        __half* nlo = hs_lo[(l + 1) & 1];
        const long loffG = (long)l * 3 * CC * CC;

        // 1) s[b][n][c] = adjT[b] @ (hT_hi + hT_lo)  -> fp16 hi/lo
        adj_mma<<<dim3(1, NN / 256, BB), 256, SMEM_ADJ>>>(
            p_adjT, p_hThi, p_hTlo, p_shi, p_slo,
            NN, NN, ROWS, CC,
            (long)NN * NN, (long)NN, (long)NN * CC);

        // 2) gx = s @ Vt^T + b_ih ; gh = h @ w_hh^T + b_hh  (merged)
        gate_mma<<<dim3(3, ROWS / 256, 2), 256, SMEM_GATE>>>(
            p_shi, p_slo, p_Vthi + loffG, p_Vtlo + loffG, p_gx, b_ih + (long)l * 3 * CC,
            chi,   clo,   p_whhhi + loffG, p_whhlo + loffG, p_gh, b_hh + (long)l * 3 * CC);

        // 3) GRU elementwise (+ h row-major & transposed splits for next layer)
        gru_elem4<<<ROWS / 64, 256>>>(
            p_gx, p_gh, chi, clo, nhi, nlo, p_hThi, p_hTlo,
            out, mask, (l == LL - 1) ? 1 : 0);
    }
}

// round 9
// speedup vs baseline: 1.1059x; 1.1059x over previous
#include <cuda_runtime.h>
#include <cuda_fp16.h>
#include <cstdint>

// Problem constants: B=32, N=1024, C=128, L=4
#define BB 32
#define NN 1024
#define CC 128
#define LL 4
#define ROWS (BB * NN)          // 32768
#define HSZ  (ROWS * CC)
#define GSZ  (ROWS * 3 * CC)

// fp32 scratch
__device__ __align__(16) float g_gx[GSZ];
__device__ __align__(16) float g_gh[GSZ];
// fp16 scratch
__device__ __align__(16) __half g_adjT[(size_t)BB * NN * NN];   // [b][n][j] exact
__device__ __align__(16) __half g_hA_hi[HSZ];                   // h splits (ping)
__device__ __align__(16) __half g_hA_lo[HSZ];
__device__ __align__(16) __half g_hB_hi[HSZ];                   // h splits (pong)
__device__ __align__(16) __half g_hB_lo[HSZ];
__device__ __align__(16) __half g_s_hi[HSZ];                    // s = adjT@h splits
__device__ __align__(16) __half g_s_lo[HSZ];
__device__ __align__(16) __half g_Vt_hi[LL * 3 * CC * CC];      // [l][g][c]  (W@w_ih^T)^T
__device__ __align__(16) __half g_Vt_lo[LL * 3 * CC * CC];
__device__ __align__(16) __half g_whh_hi[LL * 3 * CC * CC];
__device__ __align__(16) __half g_whh_lo[LL * 3 * CC * CC];

// ===========================================================================
// helpers
// ===========================================================================
__device__ __forceinline__ uint32_t smem_u32(const void* p) {
    uint32_t a;
    asm("{ .reg .u64 t; cvta.to.shared.u64 t, %1; cvt.u32.u64 %0, t; }"
        : "=r"(a) : "l"(p));
    return a;
}
__device__ __forceinline__ void cp16(uint32_t s, const void* g) {
    asm volatile("cp.async.cg.shared.global [%0], [%1], 16;" :: "r"(s), "l"(g));
}
#define CP_COMMIT() asm volatile("cp.async.commit_group;" ::: "memory")
#define CP_WAIT(n)  asm volatile("cp.async.wait_group %0;" :: "n"(n) : "memory")

#define LDSM4(R0, R1, R2, R3, ADDR)                                          \
    asm volatile("ldmatrix.sync.aligned.m8n8.x4.shared.b16 {%0,%1,%2,%3}, [%4];" \
                 : "=r"(R0), "=r"(R1), "=r"(R2), "=r"(R3) : "r"(ADDR))

#define LDSM4T(R0, R1, R2, R3, ADDR)                                         \
    asm volatile("ldmatrix.sync.aligned.m8n8.x4.trans.shared.b16 {%0,%1,%2,%3}, [%4];" \
                 : "=r"(R0), "=r"(R1), "=r"(R2), "=r"(R3) : "r"(ADDR))

#define MMA16816(D, A, B0, B1)                                               \
    asm volatile(                                                            \
        "mma.sync.aligned.m16n8k16.row.col.f32.f16.f16.f32 "                 \
        "{%0,%1,%2,%3},{%4,%5,%6,%7},{%8,%9},{%0,%1,%2,%3};"                 \
        : "+f"((D)[0]), "+f"((D)[1]), "+f"((D)[2]), "+f"((D)[3])             \
        : "r"((A)[0]), "r"((A)[1]), "r"((A)[2]), "r"((A)[3]),                \
          "r"(B0), "r"(B1))

// Load an R-row x 64-col fp16 tile (128B rows, XOR-16B swizzle) via cp.async.
template <int R>
__device__ __forceinline__ void cp_tile(const __half* __restrict__ g,
                                        int stride, uint32_t sdst, int t, int kc)
{
    #pragma unroll
    for (int u = 0; u < R / 32; ++u) {
        const int unit = t + u * 256;
        const int row  = unit >> 3;
        const int c16  = unit & 7;
        const uint32_t sw = ((row << 7) + (c16 << 4)) ^ ((row & 7) << 4);
        cp16(sdst + sw, g + (size_t)row * stride + (kc << 6) + (c16 << 3));
    }
}

// Load a 64-row x 128-col fp16 tile (256B rows, per-row XOR swizzle) for
// trans-ldmatrix consumption. g pre-offset to the first row; stride in elems.
__device__ __forceinline__ void cp_tile_kn(const __half* __restrict__ g,
                                           int stride, uint32_t sdst, int t)
{
    #pragma unroll
    for (int u = 0; u < 4; ++u) {
        const int unit = t + u * 256;          // 0..1023
        const int row  = unit >> 4;            // 0..63
        const int c16  = unit & 15;            // 16B col within 256B row
        const uint32_t sw = (row << 8) + (((uint32_t)(c16 ^ (row & 7))) << 4);
        cp16(sdst + sw, g + (size_t)row * stride + (c16 << 3));
    }
}

// ===========================================================================
// adj GEMM: CTA 256x128, warp 64x64, 3-stage pipeline.
//   s[b][n][c] = sum_j adjT[b][n][j] * (h_hi + h_lo)[b*N+j][c]
// A = adjT (K-major rows). B = h row-major [j][c], consumed via ldmatrix.trans.
// Out: fp16 hi/lo split.
// ===========================================================================
__global__ __launch_bounds__(256)
void adj_mma(const __half* __restrict__ a, const __half* __restrict__ b_hi,
             const __half* __restrict__ b_lo,
             __half* __restrict__ Chi, __half* __restrict__ Clo)
{
    constexpr uint32_t ATSZ = 32768;   // 256 x 64 fp16
    constexpr uint32_t BTSZ = 16384;   // 64 x 128 fp16
    constexpr uint32_t STG  = ATSZ + 2 * BTSZ;   // 64 KB, 3 stages = 192 KB
    extern __shared__ __align__(128) char smem[];
    const uint32_t sbase = smem_u32(smem);

    const int t     = threadIdx.x;
    const int lane  = t & 31;
    const int warp  = t >> 5;
    const int mwarp = (warp >> 1) * 64;
    const int nwarp = (warp & 1) * 64;
    const int m0 = blockIdx.y * 256;   // n-tile of adjT
    const int z  = blockIdx.x;         // batch

    const __half* Ag = a + (size_t)z * NN * NN + (size_t)m0 * NN;
    const __half* Bh = b_hi + (size_t)z * NN * CC;
    const __half* Bl = b_lo + (size_t)z * NN * CC;

    constexpr int NC = NN >> 6;   // 16

    float acc[4][8][4];
    #pragma unroll
    for (int i = 0; i < 4; i++)
        #pragma unroll
        for (int j = 0; j < 8; j++)
            #pragma unroll
            for (int q = 0; q < 4; q++)
                acc[i][j][q] = 0.0f;

    auto load_stage = [&](int kc, uint32_t sb) {
        cp_tile<256>(Ag, NN, sb, t, kc);
        cp_tile_kn(Bh + (size_t)(kc << 6) * CC, CC, sb + ATSZ, t);
        cp_tile_kn(Bl + (size_t)(kc << 6) * CC, CC, sb + ATSZ + BTSZ, t);
        CP_COMMIT();
    };

    load_stage(0, sbase);
    load_stage(1, sbase + STG);

    for (int c = 0; c < NC; ++c) {
        const int nxt = c + 2;
        if (nxt < NC) load_stage(nxt, sbase + (nxt % 3) * STG);
        const int nleft = NC - 1 - c;
        if (nleft >= 2)      CP_WAIT(2);
        else if (nleft == 1) CP_WAIT(1);
        else                 CP_WAIT(0);
        __syncthreads();

        const uint32_t S  = sbase + (c % 3) * STG;
        const uint32_t Bb = S + ATSZ;

        #pragma unroll
        for (int ks = 0; ks < 4; ++ks) {
            // ---- A fragments (adjT, K-major, non-trans) ----
            uint32_t ah[4][4];
            #pragma unroll
            for (int mb = 0; mb < 4; ++mb) {
                const int row = mwarp + mb * 16 + (lane & 15);
                const int col = ks * 32 + ((lane >> 4) << 4);
                const uint32_t sw = (row << 7) + (col ^ ((row & 7) << 4));
                LDSM4(ah[mb][0], ah[mb][1], ah[mb][2], ah[mb][3], S + sw);
            }
            // ---- B fragments from row-major h tiles via ldmatrix.trans ----
            // matrix0: k 0-7 / n 0-7; matrix1: k 8-15 / n 0-7;
            // matrix2: k 0-7 / n 8-15; matrix3: k 8-15 / n 8-15
            uint32_t bh[4][4], bl[4][4];
            #pragma unroll
            for (int nq = 0; nq < 4; ++nq) {
                const int rk  = ks * 16 + ((lane >> 3) & 1) * 8 + (lane & 7);
                const int cc  = nwarp + nq * 16 + (lane >> 4) * 8;
                const uint32_t c16 = (uint32_t)(cc >> 3);
                const uint32_t sw  = (rk << 8) + ((c16 ^ (rk & 7)) << 4);
                LDSM4T(bh[nq][0], bh[nq][1], bh[nq][2], bh[nq][3], Bb + sw);
                LDSM4T(bl[nq][0], bl[nq][1], bl[nq][2], bl[nq][3], Bb + BTSZ + sw);
            }
            #pragma unroll
            for (int mb = 0; mb < 4; ++mb)
                #pragma unroll
                for (int n = 0; n < 8; ++n) {
                    const int q0 = (n & 1) * 2;
                    MMA16816(acc[mb][n], ah[mb], bh[n >> 1][q0], bh[n >> 1][q0 + 1]);
                    MMA16816(acc[mb][n], ah[mb], bl[n >> 1][q0], bl[n >> 1][q0 + 1]);
                }
        }
        __syncthreads();
    }

    // epilogue: fp16 hi/lo split of s
    const int rbase = m0 + mwarp + (lane >> 2);
    const int cbase = nwarp + (lane & 3) * 2;
    __half* CH = Chi + (size_t)z * NN * CC;
    __half* CL = Clo + (size_t)z * NN * CC;
    #pragma unroll
    for (int mb = 0; mb < 4; ++mb) {
        #pragma unroll
        for (int n = 0; n < 8; ++n) {
            const int gc = cbase + n * 8;
            const int r  = rbase + mb * 16;
            #pragma unroll
            for (int hf = 0; hf < 2; ++hf) {
                const float v0 = acc[mb][n][hf * 2 + 0];
                const float v1 = acc[mb][n][hf * 2 + 1];
                const __half h0 = __float2half_rn(v0);
                const __half h1 = __float2half_rn(v1);
                __half2 ph; ph.x = h0; ph.y = h1;
                __half2 pl;
                pl.x = __float2half_rn(v0 - __half2float(h0));
                pl.y = __float2half_rn(v1 - __half2float(h1));
                const size_t off = (size_t)(r + hf * 8) * CC + gc;
                *reinterpret_cast<__half2*>(&CH[off]) = ph;
                *reinterpret_cast<__half2*>(&CL[off]) = pl;
            }
        }
    }
}

// ===========================================================================
// Merged gate GEMMs: grid.z selects (A,B,C,bias) set.
//   C = Ahi@Bhi^T + Ahi@Blo^T + Alo@Bhi^T + bias   (fp32 out, ldc=384)
// CTA 256x128, warp 64x64, 2-stage. K=128 (NC=2).
// ===========================================================================
__global__ __launch_bounds__(256)
void gate_mma(const __half* __restrict__ a0h, const __half* __restrict__ a0l,
              const __half* __restrict__ b0h, const __half* __restrict__ b0l,
              float* __restrict__ C0, const float* __restrict__ bias0,
              const __half* __restrict__ a1h, const __half* __restrict__ a1l,
              const __half* __restrict__ b1h, const __half* __restrict__ b1l,
              float* __restrict__ C1, const float* __restrict__ bias1)
{
    constexpr uint32_t ATSZ = 32768;
    constexpr uint32_t BTSZ = 16384;
    constexpr uint32_t STG  = 2 * ATSZ + 2 * BTSZ;   // 96 KB, 2 stages = 192 KB
    extern __shared__ __align__(128) char smem[];
    const uint32_t sbase = smem_u32(smem);

    const int t     = threadIdx.x;
    const int lane  = t & 31;
    const int warp  = t >> 5;
    const int mwarp = (warp >> 1) * 64;
    const int nwarp = (warp & 1) * 64;
    const int m0 = blockIdx.y * 256;
    const int n0 = blockIdx.x * 128;
    const int z  = blockIdx.z;

    const __half* Ah = (z == 0 ? a0h : a1h) + (size_t)m0 * CC;
    const __half* Al = (z == 0 ? a0l : a1l) + (size_t)m0 * CC;
    const __half* Bh = (z == 0 ? b0h : b1h) + (size_t)n0 * CC;
    const __half* Bl = (z == 0 ? b0l : b1l) + (size_t)n0 * CC;
    float* C = (z == 0 ? C0 : C1);
    const float* bias = (z == 0 ? bias0 : bias1);

    constexpr int NC = 2;   // K = 128

    float acc[4][8][4];
    #pragma unroll
    for (int i = 0; i < 4; i++)
        #pragma unroll
        for (int j = 0; j < 8; j++)
            #pragma unroll
            for (int q = 0; q < 4; q++)
                acc[i][j][q] = 0.0f;

    auto load_stage = [&](int kc, uint32_t sb) {
        cp_tile<256>(Ah, CC, sb, t, kc);
        cp_tile<256>(Al, CC, sb + ATSZ, t, kc);
        cp_tile<128>(Bh, CC, sb + 2 * ATSZ, t, kc);
        cp_tile<128>(Bl, CC, sb + 2 * ATSZ + BTSZ, t, kc);
        CP_COMMIT();
    };

    load_stage(0, sbase);
    load_stage(1, sbase + STG);

    #pragma unroll
    for (int c = 0; c < NC; ++c) {
        if (c == 0) CP_WAIT(1); else CP_WAIT(0);
        __syncthreads();

        const uint32_t S = sbase + c * STG;
        const uint32_t Bb = S + 2 * ATSZ;

        #pragma unroll
        for (int ks = 0; ks < 4; ++ks) {
            uint32_t ah[4][4], al[4][4];
            #pragma unroll
            for (int mb = 0; mb < 4; ++mb) {
                const int row = mwarp + mb * 16 + (lane & 15);
                const int col = ks * 32 + ((lane >> 4) << 4);
                const uint32_t sw = (row << 7) + (col ^ ((row & 7) << 4));
                LDSM4(ah[mb][0], ah[mb][1], ah[mb][2], ah[mb][3], S + sw);
                LDSM4(al[mb][0], al[mb][1], al[mb][2], al[mb][3], S + ATSZ + sw);
            }
            uint32_t bh[4][4], bl[4][4];
            #pragma unroll
            for (int nq = 0; nq < 4; ++nq) {
                const int row = nwarp + nq * 16 + ((lane >> 4) << 3) + (lane & 7);
                const int col = ks * 32 + (((lane >> 3) & 1) << 4);
                const uint32_t sw = (row << 7) + (col ^ ((row & 7) << 4));
                LDSM4(bh[nq][0], bh[nq][1], bh[nq][2], bh[nq][3], Bb + sw);
                LDSM4(bl[nq][0], bl[nq][1], bl[nq][2], bl[nq][3], Bb + BTSZ + sw);
            }
            #pragma unroll
            for (int mb = 0; mb < 4; ++mb)
                #pragma unroll
                for (int n = 0; n < 8; ++n) {
                    const int q0 = (n & 1) * 2;
                    MMA16816(acc[mb][n], ah[mb], bh[n >> 1][q0], bh[n >> 1][q0 + 1]);
                    MMA16816(acc[mb][n], ah[mb], bl[n >> 1][q0], bl[n >> 1][q0 + 1]);
                    MMA16816(acc[mb][n], al[mb], bh[n >> 1][q0], bh[n >> 1][q0 + 1]);
                }
        }
        __syncthreads();
    }

    const int rbase = m0 + mwarp + (lane >> 2);
    const int cbase = n0 + nwarp + (lane & 3) * 2;
    #pragma unroll
    for (int mb = 0; mb < 4; ++mb) {
        #pragma unroll
        for (int n = 0; n < 8; ++n) {
            const int gc = cbase + n * 8;
            const float bx = bias[gc];
            const float by = bias[gc + 1];
            const int r = rbase + mb * 16;
            float2 v0 = { acc[mb][n][0] + bx, acc[mb][n][1] + by };
            float2 v1 = { acc[mb][n][2] + bx, acc[mb][n][3] + by };
            *reinterpret_cast<float2*>(&C[(size_t)r * (3 * CC) + gc])       = v0;
            *reinterpret_cast<float2*>(&C[(size_t)(r + 8) * (3 * CC) + gc]) = v1;
        }
    }
}

// ===========================================================================
// Prep kernels
// ===========================================================================
__global__ __launch_bounds__(256)
void adj_transpose(const float* __restrict__ adj, __half* __restrict__ adjT)
{
    __shared__ float tile[32][33];
    const int b  = blockIdx.z;
    const int j0 = blockIdx.x * 32;
    const int n0 = blockIdx.y * 32;
    const float* src = adj + (size_t)b * NN * NN;
    __half* dst = adjT + (size_t)b * NN * NN;
    const int tx = threadIdx.x & 31, ty = threadIdx.x >> 5;
    #pragma unroll
    for (int r = ty; r < 32; r += 8)
        tile[r][tx] = src[(size_t)(j0 + r) * NN + n0 + tx];
    __syncthreads();
    #pragma unroll
    for (int r = ty; r < 32; r += 8)
        dst[(size_t)(n0 + r) * NN + j0 + tx] = __float2half_rn(tile[tx][r]);
}

__global__ __launch_bounds__(256)
void split2(const float* __restrict__ x,
            __half* __restrict__ hi, __half* __restrict__ lo)
{
    const int i = blockIdx.x * blockDim.x + threadIdx.x;
    const float v = x[i];
    const __half h = __float2half_rn(v);
    hi[i] = h;
    lo[i] = __float2half_rn(v - __half2float(h));
}

// Vt[l][g][c] = sum_d w_ih[l][g][d] * W[l][c][d], split hi/lo.
__global__ __launch_bounds__(256)
void vt_prep(const float* __restrict__ W, const float* __restrict__ w_ih,
             __half* __restrict__ Vthi, __half* __restrict__ Vtlo)
{
    const int l   = blockIdx.z;
    const int idx = blockIdx.x * 256 + threadIdx.x;   // < 384*128
    const int g = idx >> 7;
    const int c = idx & 127;
    const float* wi = w_ih + (size_t)l * 3 * CC * CC + (size_t)g * CC;
    const float* wc = W    + (size_t)l * CC * CC + (size_t)c * CC;
    float s = 0.0f;
    #pragma unroll 8
    for (int d = 0; d < CC; ++d)
        s = fmaf(wi[d], wc[d], s);
    const __half h = __float2half_rn(s);
    const size_t o = (size_t)l * 3 * CC * CC + idx;
    Vthi[o] = h;
    Vtlo[o] = __float2half_rn(s - __half2float(h));
}

// ===========================================================================
// Fused GRU elementwise: h stored as fp16 hi/lo splits only (streaming).
// ===========================================================================
__global__ __launch_bounds__(256)
void gru_elem3(const float* __restrict__ gx, const float* __restrict__ gh,
               const __half* __restrict__ hhi_in, const __half* __restrict__ hlo_in,
               __half* __restrict__ hhi_out, __half* __restrict__ hlo_out,
               float* __restrict__ outF,
               const float* __restrict__ mask, int isLast)
{
    const int idx = blockIdx.x * blockDim.x + threadIdx.x;
    const int r = idx >> 7;
    const int c = idx & 127;

    const long gbase = (long)r * (3 * CC);
    const float xr = gx[gbase + c];
    const float xz = gx[gbase + CC + c];
    const float xn = gx[gbase + 2 * CC + c];
    const float hr = gh[gbase + c];
    const float hz = gh[gbase + CC + c];
    const float hn = gh[gbase + 2 * CC + c];

    const float h = __half2float(hhi_in[idx]) + __half2float(hlo_in[idx]);

    const float rg = 1.0f / (1.0f + __expf(-(xr + hr)));
    const float zg = 1.0f / (1.0f + __expf(-(xz + hz)));
    const float ng = tanhf(xn + rg * hn);
    const float hnew = (1.0f - zg) * ng + zg * h;

    if (isLast) {
        outF[idx] = hnew * mask[r];
    } else {
        const __half hb = __float2half_rn(hnew);
        hhi_out[idx] = hb;
        hlo_out[idx] = __float2half_rn(hnew - __half2float(hb));
    }
}

// ===========================================================================
#define SMEM_ADJ   (3 * (32768 + 2 * 16384))         // 192 KB (3 stages)
#define SMEM_GATE  (2 * (2 * 32768 + 2 * 16384))     // 192 KB (2 stages)

extern "C" void kernel_launch(void* const* d_in, const int* in_sizes, int n_in,
                              void* d_out, int out_size)
{
    const float* x      = (const float*)d_in[0];
    const float* adj    = (const float*)d_in[1];
    const float* mask   = (const float*)d_in[2];
    const float* weight = (const float*)d_in[3];
    const float* w_ih   = (const float*)d_in[4];
    const float* w_hh   = (const float*)d_in[5];
    const float* b_ih   = (const float*)d_in[6];
    const float* b_hh   = (const float*)d_in[7];
    float* out = (float*)d_out;

    float *p_gx, *p_gh;
    __half *p_adjT, *p_shi, *p_slo;
    __half *p_hAhi, *p_hAlo, *p_hBhi, *p_hBlo;
    __half *p_Vthi, *p_Vtlo, *p_whhhi, *p_whhlo;
    cudaGetSymbolAddress((void**)&p_gx, g_gx);
    cudaGetSymbolAddress((void**)&p_gh, g_gh);
    cudaGetSymbolAddress((void**)&p_adjT, g_adjT);
    cudaGetSymbolAddress((void**)&p_shi, g_s_hi);
    cudaGetSymbolAddress((void**)&p_slo, g_s_lo);
    cudaGetSymbolAddress((void**)&p_hAhi, g_hA_hi);
    cudaGetSymbolAddress((void**)&p_hAlo, g_hA_lo);
    cudaGetSymbolAddress((void**)&p_hBhi, g_hB_hi);
    cudaGetSymbolAddress((void**)&p_hBlo, g_hB_lo);
    cudaGetSymbolAddress((void**)&p_Vthi, g_Vt_hi);
    cudaGetSymbolAddress((void**)&p_Vtlo, g_Vt_lo);
    cudaGetSymbolAddress((void**)&p_whhhi, g_whh_hi);
    cudaGetSymbolAddress((void**)&p_whhlo, g_whh_lo);

    cudaFuncSetAttribute(adj_mma,  cudaFuncAttributeMaxDynamicSharedMemorySize, SMEM_ADJ);
    cudaFuncSetAttribute(gate_mma, cudaFuncAttributeMaxDynamicSharedMemorySize, SMEM_GATE);

    // ---- once per call ----
    adj_transpose<<<dim3(NN / 32, NN / 32, BB), 256>>>(adj, p_adjT);
    vt_prep<<<dim3((3 * CC * CC) / 256, 1, LL), 256>>>(weight, w_ih, p_Vthi, p_Vtlo);
    split2<<<(LL * 3 * CC * CC) / 256, 256>>>(w_hh, p_whhhi, p_whhlo);
    split2<<<HSZ / 256, 256>>>(x, p_hAhi, p_hAlo);   // h0 = x

    __half* hs_hi[2] = { p_hAhi, p_hBhi };
    __half* hs_lo[2] = { p_hAlo, p_hBlo };

    for (int l = 0; l < LL; l++) {
        __half* chi = hs_hi[l & 1];
        __half* clo = hs_lo[l & 1];
        __half* nhi = hs_hi[(l + 1) & 1];
        __half* nlo = hs_lo[(l + 1) & 1];
        const long loffG = (long)l * 3 * CC * CC;

        // 1) s[b][n][c] = adjT[b] @ h[b]   (h row-major via ldmatrix.trans)
        adj_mma<<<dim3(BB, NN / 256), 256, SMEM_ADJ>>>(
            p_adjT, chi, clo, p_shi, p_slo);

        // 2) gx = s @ Vt^T + b_ih ; gh = h @ w_hh^T + b_hh  (merged)
        gate_mma<<<dim3(3, ROWS / 256, 2), 256, SMEM_GATE>>>(
            p_shi, p_slo, p_Vthi + loffG, p_Vtlo + loffG, p_gx, b_ih + (long)l * 3 * CC,
            chi,   clo,   p_whhhi + loffG, p_whhlo + loffG, p_gh, b_hh + (long)l * 3 * CC);

        // 3) GRU elementwise (streaming)
        gru_elem3<<<(ROWS * CC) / 256, 256>>>(
            p_gx, p_gh, chi, clo, nhi, nlo, out, mask, (l == LL - 1) ? 1 : 0);
    }
}